// round 5
// baseline (speedup 1.0000x reference)
#include <cuda_runtime.h>
#include <cuda_bf16.h>

// auxiliary_loss: loss = 0.2 * (pos*sum_neg - neg*sum_pos) / (pos*neg)
// R5: contiguous per-CTA chunks + 4-deep unroll (8 LDG.128 in flight/thread,
// all within a ~1-3KB neighborhood -> DRAM row locality), fused last-block
// finalize. Scan is SM-level MLP-limited (16KB in flight < lat*BW ~21KB).

#define DETA 0.2

constexpr int RED_BLOCKS  = 1184;   // 148 SMs * 8 CTAs
constexpr int RED_THREADS = 256;

// Scratch (__device__ globals; no allocation).
__device__ float        g_psum_all[RED_BLOCKS];
__device__ float        g_psum_pos[RED_BLOCKS];
__device__ int          g_pcnt[RED_BLOCKS];
__device__ unsigned int g_done = 0;   // reset by last block each call

__device__ __forceinline__ float warp_red_f(float v) {
    #pragma unroll
    for (int o = 16; o > 0; o >>= 1) v += __shfl_down_sync(0xffffffffu, v, o);
    return v;
}
__device__ __forceinline__ int warp_red_i(int v) {
    #pragma unroll
    for (int o = 16; o > 0; o >>= 1) v += __shfl_down_sync(0xffffffffu, v, o);
    return v;
}
__device__ __forceinline__ double warp_red_d(double v) {
    #pragma unroll
    for (int o = 16; o > 0; o >>= 1) v += __shfl_down_sync(0xffffffffu, v, o);
    return v;
}

__global__ __launch_bounds__(RED_THREADS)
void fused_loss_kernel(const float4* __restrict__ y4,
                       const int4*   __restrict__ l4,
                       int nvec,
                       const float* __restrict__ ytail,
                       const int*   __restrict__ ltail,
                       int tail,
                       float* __restrict__ out,
                       double n_total)
{
    // Contiguous chunk per CTA.
    const int chunk = (nvec + (int)gridDim.x - 1) / (int)gridDim.x;
    const int start = blockIdx.x * chunk;
    const int end   = min(start + chunk, nvec);

    float sa0 = 0.0f, sa1 = 0.0f, sp0 = 0.0f, sp1 = 0.0f;
    int   c0 = 0, c1 = 0;

    int i = start + (int)threadIdx.x;

    // 4-deep unroll: 8 independent LDG.128 fronted per thread, all within
    // a 3*256*16B = 12KB window of this CTA's contiguous chunk.
    for (; i + 3 * RED_THREADS < end; i += 4 * RED_THREADS) {
        float4 v0 = __ldcs(&y4[i]);
        float4 v1 = __ldcs(&y4[i +     RED_THREADS]);
        float4 v2 = __ldcs(&y4[i + 2 * RED_THREADS]);
        float4 v3 = __ldcs(&y4[i + 3 * RED_THREADS]);
        int4   l0 = __ldcs(&l4[i]);
        int4   l1 = __ldcs(&l4[i +     RED_THREADS]);
        int4   l2 = __ldcs(&l4[i + 2 * RED_THREADS]);
        int4   l3 = __ldcs(&l4[i + 3 * RED_THREADS]);

        sa0 += (v0.x + v0.y) + (v0.z + v0.w);
        sa1 += (v1.x + v1.y) + (v1.z + v1.w);
        sa0 += (v2.x + v2.y) + (v2.z + v2.w);
        sa1 += (v3.x + v3.y) + (v3.z + v3.w);

        float p0 = 0.0f, p1 = 0.0f;
        if (l0.x) p0 += v0.x;
        if (l0.y) p0 += v0.y;
        if (l0.z) p0 += v0.z;
        if (l0.w) p0 += v0.w;
        if (l1.x) p1 += v1.x;
        if (l1.y) p1 += v1.y;
        if (l1.z) p1 += v1.z;
        if (l1.w) p1 += v1.w;
        if (l2.x) p0 += v2.x;
        if (l2.y) p0 += v2.y;
        if (l2.z) p0 += v2.z;
        if (l2.w) p0 += v2.w;
        if (l3.x) p1 += v3.x;
        if (l3.y) p1 += v3.y;
        if (l3.z) p1 += v3.z;
        if (l3.w) p1 += v3.w;
        sp0 += p0; sp1 += p1;

        c0 += (l0.x + l0.y) + (l0.z + l0.w) + (l2.x + l2.y) + (l2.z + l2.w);
        c1 += (l1.x + l1.y) + (l1.z + l1.w) + (l3.x + l3.y) + (l3.z + l3.w);
    }
    // Remainder
    for (; i < end; i += RED_THREADS) {
        float4 v = __ldcs(&y4[i]);
        int4   l = __ldcs(&l4[i]);
        sa0 += (v.x + v.y) + (v.z + v.w);
        float p = 0.0f;
        if (l.x) p += v.x;
        if (l.y) p += v.y;
        if (l.z) p += v.z;
        if (l.w) p += v.w;
        sp0 += p;
        c0  += l.x + l.y + l.z + l.w;
    }

    float sa = sa0 + sa1;
    float sp = sp0 + sp1;
    int   c  = c0 + c1;

    // Scalar tail (n % 4), handled once by block 0.
    if (blockIdx.x == 0 && (int)threadIdx.x < tail) {
        float v = ytail[threadIdx.x];
        int   l = ltail[threadIdx.x];
        sa += v;
        if (l) { sp += v; c += 1; }
    }

    // Intra-block reduce
    sa = warp_red_f(sa);
    sp = warp_red_f(sp);
    c  = warp_red_i(c);

    __shared__ float s_sa[RED_THREADS / 32];
    __shared__ float s_sp[RED_THREADS / 32];
    __shared__ int   s_c [RED_THREADS / 32];
    __shared__ bool  s_last;
    int wid = threadIdx.x >> 5;
    int lid = threadIdx.x & 31;
    if (lid == 0) { s_sa[wid] = sa; s_sp[wid] = sp; s_c[wid] = c; }
    __syncthreads();

    if (wid == 0) {
        constexpr int NW = RED_THREADS / 32;
        float a = (lid < NW) ? s_sa[lid] : 0.0f;
        float p = (lid < NW) ? s_sp[lid] : 0.0f;
        int   k = (lid < NW) ? s_c [lid] : 0;
        a = warp_red_f(a);
        p = warp_red_f(p);
        k = warp_red_i(k);
        if (lid == 0) {
            g_psum_all[blockIdx.x] = a;
            g_psum_pos[blockIdx.x] = p;
            g_pcnt[blockIdx.x]     = k;
            __threadfence();
            unsigned int t = atomicAdd(&g_done, 1u);
            s_last = (t == (unsigned int)(gridDim.x - 1));
        }
    }
    __syncthreads();

    if (!s_last) return;

    // ---- Last block: finalize (partials L2-hot). Deterministic order. ----
    double dsa = 0.0, dsp = 0.0;
    long long dc = 0;
    for (int j = threadIdx.x; j < RED_BLOCKS; j += RED_THREADS) {
        dsa += (double)g_psum_all[j];
        dsp += (double)g_psum_pos[j];
        dc  += (long long)g_pcnt[j];
    }
    dsa = warp_red_d(dsa);
    dsp = warp_red_d(dsp);
    #pragma unroll
    for (int o = 16; o > 0; o >>= 1) dc += __shfl_down_sync(0xffffffffu, dc, o);

    __shared__ double d_sa[RED_THREADS / 32], d_sp[RED_THREADS / 32];
    __shared__ long long d_c[RED_THREADS / 32];
    if (lid == 0) { d_sa[wid] = dsa; d_sp[wid] = dsp; d_c[wid] = dc; }
    __syncthreads();

    if (threadIdx.x == 0) {
        double SA = 0.0, SP = 0.0;
        long long C = 0;
        #pragma unroll
        for (int j = 0; j < RED_THREADS / 32; j++) { SA += d_sa[j]; SP += d_sp[j]; C += d_c[j]; }

        double pos = (double)C;
        double neg = n_total - pos;
        bool valid = (pos > 0.0) && (neg > 0.0);
        double sum_neg = SA - SP;
        double denom = valid ? pos * neg : 1.0;
        double loss = DETA * (pos * sum_neg - neg * SP) / denom;
        out[0] = valid ? (float)loss : 0.0f;

        g_done = 0;   // reset for next graph replay
    }
}

extern "C" void kernel_launch(void* const* d_in, const int* in_sizes, int n_in,
                              void* d_out, int out_size)
{
    const float* y   = (const float*)d_in[0];
    const int*   lab = (const int*)d_in[1];
    int n = in_sizes[0];

    int nvec = n >> 2;
    int tail = n & 3;
    const float* ytail = y + ((long long)nvec << 2);
    const int*   ltail = lab + ((long long)nvec << 2);

    fused_loss_kernel<<<RED_BLOCKS, RED_THREADS>>>(
        (const float4*)y, (const int4*)lab, nvec, ytail, ltail, tail,
        (float*)d_out, (double)n);
}

// round 6
// speedup vs baseline: 1.1392x; 1.1392x over previous
#include <cuda_runtime.h>
#include <cuda_bf16.h>
#include <cstdint>

// auxiliary_loss: loss = 0.2 * (pos*sum_neg - neg*sum_pos) / (pos*neg)
// R6: cp.async.bulk (TMA bulk) -> SMEM 3-stage pipeline. LDG-path variants all
// plateau at ~5.7TB/s (72%); bulk-async gives ~128KB in-flight DRAM per SM with
// no per-warp load limits. 148 persistent CTAs x 512 thr, 32KB+32KB tiles.

#define DETA 0.2

constexpr int NUM_CTAS   = 148;
constexpr int THREADS    = 512;
constexpr int TILE_ELEMS = 8192;                  // 32KB floats + 32KB ints
constexpr int STAGES     = 3;
constexpr int EPT        = TILE_ELEMS / THREADS;  // 16 elems/thread (4x vec4)
constexpr uint32_t TILE_Y_BYTES = TILE_ELEMS * 4;
constexpr uint32_t TILE_BYTES_TOTAL = TILE_Y_BYTES * 2;

// dynamic smem: [ y stages | l stages | mbarriers ]
constexpr int SMEM_Y_OFF = 0;
constexpr int SMEM_L_OFF = STAGES * (int)TILE_Y_BYTES;                 // 96KB
constexpr int SMEM_MBAR_OFF = SMEM_L_OFF + STAGES * (int)TILE_Y_BYTES; // 192KB
constexpr int SMEM_TOTAL = SMEM_MBAR_OFF + STAGES * 8 + 64;

// Scratch (__device__ globals; no allocation).
__device__ float        g_psum_all[NUM_CTAS];
__device__ float        g_psum_pos[NUM_CTAS];
__device__ int          g_pcnt[NUM_CTAS];
__device__ unsigned int g_done = 0;   // reset by last block each call

__device__ __forceinline__ float warp_red_f(float v) {
    #pragma unroll
    for (int o = 16; o > 0; o >>= 1) v += __shfl_down_sync(0xffffffffu, v, o);
    return v;
}
__device__ __forceinline__ int warp_red_i(int v) {
    #pragma unroll
    for (int o = 16; o > 0; o >>= 1) v += __shfl_down_sync(0xffffffffu, v, o);
    return v;
}
__device__ __forceinline__ double warp_red_d(double v) {
    #pragma unroll
    for (int o = 16; o > 0; o >>= 1) v += __shfl_down_sync(0xffffffffu, v, o);
    return v;
}

__device__ __forceinline__ uint32_t smem_u32(const void* p) {
    return (uint32_t)__cvta_generic_to_shared(p);
}
__device__ __forceinline__ void mbar_init(uint32_t mbar, uint32_t count) {
    asm volatile("mbarrier.init.shared.b64 [%0], %1;" :: "r"(mbar), "r"(count) : "memory");
}
__device__ __forceinline__ void mbar_expect_tx(uint32_t mbar, uint32_t bytes) {
    asm volatile("mbarrier.arrive.expect_tx.shared.b64 _, [%0], %1;"
                 :: "r"(mbar), "r"(bytes) : "memory");
}
__device__ __forceinline__ void mbar_wait_parity(uint32_t mbar, uint32_t parity) {
    asm volatile(
        "{\n\t"
        ".reg .pred P;\n\t"
        "W_%=:\n\t"
        "mbarrier.try_wait.parity.acquire.cta.shared::cta.b64 P, [%0], %1, 0x989680;\n\t"
        "@!P bra W_%=;\n\t"
        "}"
        :: "r"(mbar), "r"(parity) : "memory");
}
__device__ __forceinline__ void bulk_g2s(uint32_t dst_smem, const void* src, uint32_t bytes,
                                         uint32_t mbar) {
    asm volatile(
        "cp.async.bulk.shared::cluster.global.mbarrier::complete_tx::bytes [%0], [%1], %2, [%3];"
        :: "r"(dst_smem), "l"(src), "r"(bytes), "r"(mbar) : "memory");
}

__global__ __launch_bounds__(THREADS, 1)
void fused_loss_tma_kernel(const float* __restrict__ y,
                           const int*   __restrict__ lab,
                           int n,
                           float* __restrict__ out,
                           double n_total)
{
    extern __shared__ char smem[];
    float* sm_y = (float*)(smem + SMEM_Y_OFF);
    int*   sm_l = (int*)(smem + SMEM_L_OFF);
    uint32_t mbar0 = smem_u32(smem + SMEM_MBAR_OFF);

    const int tid = threadIdx.x;
    const int ntiles = n / TILE_ELEMS;

    // Tiles assigned round-robin: tile k of this CTA = blockIdx.x + k*gridDim.x
    int my_tiles = 0;
    if ((int)blockIdx.x < ntiles)
        my_tiles = (ntiles - blockIdx.x + gridDim.x - 1) / gridDim.x;

    if (tid == 0) {
        #pragma unroll
        for (int s = 0; s < STAGES; s++) mbar_init(mbar0 + s * 8, 1);
    }
    __syncthreads();

    // Prologue: fill up to STAGES tiles.
    if (tid == 0) {
        int pre = my_tiles < STAGES ? my_tiles : STAGES;
        for (int k = 0; k < pre; k++) {
            long long t = (long long)blockIdx.x + (long long)k * gridDim.x;
            uint32_t mb = mbar0 + k * 8;
            mbar_expect_tx(mb, TILE_BYTES_TOTAL);
            bulk_g2s(smem_u32(sm_y + k * TILE_ELEMS), y   + t * TILE_ELEMS, TILE_Y_BYTES, mb);
            bulk_g2s(smem_u32(sm_l + k * TILE_ELEMS), lab + t * TILE_ELEMS, TILE_Y_BYTES, mb);
        }
    }

    float sa0 = 0.0f, sa1 = 0.0f, sp0 = 0.0f, sp1 = 0.0f;
    int   c0 = 0, c1 = 0;

    for (int k = 0; k < my_tiles; k++) {
        int s = k % STAGES;
        uint32_t parity = (uint32_t)((k / STAGES) & 1);
        mbar_wait_parity(mbar0 + s * 8, parity);

        const float4* ys = (const float4*)(sm_y + s * TILE_ELEMS);
        const int4*   ls = (const int4*)(sm_l + s * TILE_ELEMS);
        #pragma unroll
        for (int j = 0; j < EPT / 4; j++) {
            float4 v = ys[tid + THREADS * j];
            int4   l = ls[tid + THREADS * j];
            if (j & 1) {
                sa1 += (v.x + v.y) + (v.z + v.w);
                float p = 0.0f;
                if (l.x) p += v.x;
                if (l.y) p += v.y;
                if (l.z) p += v.z;
                if (l.w) p += v.w;
                sp1 += p;
                c1  += l.x + l.y + l.z + l.w;
            } else {
                sa0 += (v.x + v.y) + (v.z + v.w);
                float p = 0.0f;
                if (l.x) p += v.x;
                if (l.y) p += v.y;
                if (l.z) p += v.z;
                if (l.w) p += v.w;
                sp0 += p;
                c0  += l.x + l.y + l.z + l.w;
            }
        }

        __syncthreads();   // all threads done reading stage s -> safe to refill

        if (tid == 0 && k + STAGES < my_tiles) {
            long long t = (long long)blockIdx.x + (long long)(k + STAGES) * gridDim.x;
            uint32_t mb = mbar0 + s * 8;
            mbar_expect_tx(mb, TILE_BYTES_TOTAL);
            bulk_g2s(smem_u32(sm_y + s * TILE_ELEMS), y   + t * TILE_ELEMS, TILE_Y_BYTES, mb);
            bulk_g2s(smem_u32(sm_l + s * TILE_ELEMS), lab + t * TILE_ELEMS, TILE_Y_BYTES, mb);
        }
    }

    float sa = sa0 + sa1;
    float sp = sp0 + sp1;
    int   c  = c0 + c1;

    // Remainder (n % TILE_ELEMS), handled by block 0 via plain loads.
    if (blockIdx.x == 0) {
        for (int i = ntiles * TILE_ELEMS + tid; i < n; i += THREADS) {
            float v = y[i];
            int   l = lab[i];
            sa += v;
            if (l) { sp += v; c += 1; }
        }
    }

    // Intra-block reduce
    sa = warp_red_f(sa);
    sp = warp_red_f(sp);
    c  = warp_red_i(c);

    __shared__ float s_sa[THREADS / 32];
    __shared__ float s_sp[THREADS / 32];
    __shared__ int   s_c [THREADS / 32];
    __shared__ bool  s_last;
    int wid = tid >> 5;
    int lid = tid & 31;
    if (lid == 0) { s_sa[wid] = sa; s_sp[wid] = sp; s_c[wid] = c; }
    __syncthreads();

    if (wid == 0) {
        constexpr int NW = THREADS / 32;
        float a = (lid < NW) ? s_sa[lid] : 0.0f;
        float p = (lid < NW) ? s_sp[lid] : 0.0f;
        int   k = (lid < NW) ? s_c [lid] : 0;
        a = warp_red_f(a);
        p = warp_red_f(p);
        k = warp_red_i(k);
        if (lid == 0) {
            g_psum_all[blockIdx.x] = a;
            g_psum_pos[blockIdx.x] = p;
            g_pcnt[blockIdx.x]     = k;
            __threadfence();
            unsigned int t = atomicAdd(&g_done, 1u);
            s_last = (t == (unsigned int)(gridDim.x - 1));
        }
    }
    __syncthreads();

    if (!s_last) return;

    // ---- Last block: finalize (partials L2-hot). Deterministic order. ----
    double dsa = 0.0, dsp = 0.0;
    long long dc = 0;
    for (int j = tid; j < NUM_CTAS; j += THREADS) {
        dsa += (double)g_psum_all[j];
        dsp += (double)g_psum_pos[j];
        dc  += (long long)g_pcnt[j];
    }
    dsa = warp_red_d(dsa);
    dsp = warp_red_d(dsp);
    #pragma unroll
    for (int o = 16; o > 0; o >>= 1) dc += __shfl_down_sync(0xffffffffu, dc, o);

    __shared__ double d_sa[THREADS / 32], d_sp[THREADS / 32];
    __shared__ long long d_c[THREADS / 32];
    if (lid == 0) { d_sa[wid] = dsa; d_sp[wid] = dsp; d_c[wid] = dc; }
    __syncthreads();

    if (tid == 0) {
        double SA = 0.0, SP = 0.0;
        long long C = 0;
        #pragma unroll
        for (int j = 0; j < THREADS / 32; j++) { SA += d_sa[j]; SP += d_sp[j]; C += d_c[j]; }

        double pos = (double)C;
        double neg = n_total - pos;
        bool valid = (pos > 0.0) && (neg > 0.0);
        double sum_neg = SA - SP;
        double denom = valid ? pos * neg : 1.0;
        double loss = DETA * (pos * sum_neg - neg * SP) / denom;
        out[0] = valid ? (float)loss : 0.0f;

        g_done = 0;   // reset for next graph replay
    }
}

extern "C" void kernel_launch(void* const* d_in, const int* in_sizes, int n_in,
                              void* d_out, int out_size)
{
    const float* y   = (const float*)d_in[0];
    const int*   lab = (const int*)d_in[1];
    int n = in_sizes[0];

    static bool attr_set = false;
    if (!attr_set) {
        cudaFuncSetAttribute(fused_loss_tma_kernel,
                             cudaFuncAttributeMaxDynamicSharedMemorySize, SMEM_TOTAL);
        attr_set = true;
    }

    fused_loss_tma_kernel<<<NUM_CTAS, THREADS, SMEM_TOTAL>>>(
        y, lab, n, (float*)d_out, (double)n);
}

// round 7
// speedup vs baseline: 1.1527x; 1.0118x over previous
#include <cuda_runtime.h>
#include <cuda_bf16.h>
#include <cstdint>

// auxiliary_loss: loss = 0.2 * (pos*sum_neg - neg*sum_pos) / (pos*neg)
// R7: R3 skeleton (best: 48.99us) + Blackwell 256-bit loads (ld.global.nc.v8).
// LDG / TMA / chunked variants ALL plateau at 5.7-5.8 TB/s (72% DRAM) ->
// chip-level ceiling; this halves per-byte request count as the last lever.

#define DETA 0.2

constexpr int RED_BLOCKS  = 1184;   // 148 SMs * 8 CTAs
constexpr int RED_THREADS = 256;

// Scratch (__device__ globals; no allocation).
__device__ float        g_psum_all[RED_BLOCKS];
__device__ float        g_psum_pos[RED_BLOCKS];
__device__ int          g_pcnt[RED_BLOCKS];
__device__ unsigned int g_done = 0;   // reset by last block each call

__device__ __forceinline__ float warp_red_f(float v) {
    #pragma unroll
    for (int o = 16; o > 0; o >>= 1) v += __shfl_down_sync(0xffffffffu, v, o);
    return v;
}
__device__ __forceinline__ int warp_red_i(int v) {
    #pragma unroll
    for (int o = 16; o > 0; o >>= 1) v += __shfl_down_sync(0xffffffffu, v, o);
    return v;
}
__device__ __forceinline__ double warp_red_d(double v) {
    #pragma unroll
    for (int o = 16; o > 0; o >>= 1) v += __shfl_down_sync(0xffffffffu, v, o);
    return v;
}

// 256-bit vector loads (sm_100+/sm_103a). 32B aligned, read-only, streaming.
__device__ __forceinline__ void ldg256_f32(const float* p, float* v) {
    asm volatile("ld.global.nc.v8.f32 {%0,%1,%2,%3,%4,%5,%6,%7}, [%8];"
                 : "=f"(v[0]), "=f"(v[1]), "=f"(v[2]), "=f"(v[3]),
                   "=f"(v[4]), "=f"(v[5]), "=f"(v[6]), "=f"(v[7])
                 : "l"(p));
}
__device__ __forceinline__ void ldg256_s32(const int* p, int* v) {
    asm volatile("ld.global.nc.v8.b32 {%0,%1,%2,%3,%4,%5,%6,%7}, [%8];"
                 : "=r"(v[0]), "=r"(v[1]), "=r"(v[2]), "=r"(v[3]),
                   "=r"(v[4]), "=r"(v[5]), "=r"(v[6]), "=r"(v[7])
                 : "l"(p));
}

__global__ __launch_bounds__(RED_THREADS)
void fused_loss_kernel(const float* __restrict__ y,
                       const int*   __restrict__ lab,
                       int nvec8,            // n / 8
                       int tail,             // n % 8
                       float* __restrict__ out,
                       double n_total)
{
    // Two independent accumulator banks.
    float sa0 = 0.0f, sa1 = 0.0f, sp0 = 0.0f, sp1 = 0.0f;
    int   c0 = 0, c1 = 0;

    const int stride = gridDim.x * blockDim.x;   // 303104
    for (int i = blockIdx.x * blockDim.x + threadIdx.x; i < nvec8; i += stride) {
        float v[8];
        int   l[8];
        ldg256_f32(y   + (size_t)i * 8, v);
        ldg256_s32(lab + (size_t)i * 8, l);

        sa0 += (v[0] + v[1]) + (v[2] + v[3]);
        sa1 += (v[4] + v[5]) + (v[6] + v[7]);
        float p0 = 0.0f, p1 = 0.0f;
        if (l[0]) p0 += v[0];
        if (l[1]) p0 += v[1];
        if (l[2]) p0 += v[2];
        if (l[3]) p0 += v[3];
        if (l[4]) p1 += v[4];
        if (l[5]) p1 += v[5];
        if (l[6]) p1 += v[6];
        if (l[7]) p1 += v[7];
        sp0 += p0; sp1 += p1;
        c0  += (l[0] + l[1]) + (l[2] + l[3]);
        c1  += (l[4] + l[5]) + (l[6] + l[7]);
    }

    float sa = sa0 + sa1;
    float sp = sp0 + sp1;
    int   c  = c0 + c1;

    // Scalar tail (n % 8), handled once by block 0.
    if (blockIdx.x == 0 && (int)threadIdx.x < tail) {
        const float* yt = y   + (size_t)nvec8 * 8;
        const int*   lt = lab + (size_t)nvec8 * 8;
        float v = yt[threadIdx.x];
        int   l = lt[threadIdx.x];
        sa += v;
        if (l) { sp += v; c += 1; }
    }

    // Intra-block reduce
    sa = warp_red_f(sa);
    sp = warp_red_f(sp);
    c  = warp_red_i(c);

    __shared__ float s_sa[RED_THREADS / 32];
    __shared__ float s_sp[RED_THREADS / 32];
    __shared__ int   s_c [RED_THREADS / 32];
    __shared__ bool  s_last;
    int wid = threadIdx.x >> 5;
    int lid = threadIdx.x & 31;
    if (lid == 0) { s_sa[wid] = sa; s_sp[wid] = sp; s_c[wid] = c; }
    __syncthreads();

    if (wid == 0) {
        constexpr int NW = RED_THREADS / 32;
        float a = (lid < NW) ? s_sa[lid] : 0.0f;
        float p = (lid < NW) ? s_sp[lid] : 0.0f;
        int   k = (lid < NW) ? s_c [lid] : 0;
        a = warp_red_f(a);
        p = warp_red_f(p);
        k = warp_red_i(k);
        if (lid == 0) {
            g_psum_all[blockIdx.x] = a;
            g_psum_pos[blockIdx.x] = p;
            g_pcnt[blockIdx.x]     = k;
            __threadfence();
            unsigned int t = atomicAdd(&g_done, 1u);
            s_last = (t == (unsigned int)(gridDim.x - 1));
        }
    }
    __syncthreads();

    if (!s_last) return;

    // ---- Last block: finalize (partials L2-hot). Deterministic order. ----
    double dsa = 0.0, dsp = 0.0;
    long long dc = 0;
    for (int j = threadIdx.x; j < RED_BLOCKS; j += RED_THREADS) {
        dsa += (double)g_psum_all[j];
        dsp += (double)g_psum_pos[j];
        dc  += (long long)g_pcnt[j];
    }
    dsa = warp_red_d(dsa);
    dsp = warp_red_d(dsp);
    #pragma unroll
    for (int o = 16; o > 0; o >>= 1) dc += __shfl_down_sync(0xffffffffu, dc, o);

    __shared__ double d_sa[RED_THREADS / 32], d_sp[RED_THREADS / 32];
    __shared__ long long d_c[RED_THREADS / 32];
    if (lid == 0) { d_sa[wid] = dsa; d_sp[wid] = dsp; d_c[wid] = dc; }
    __syncthreads();

    if (threadIdx.x == 0) {
        double SA = 0.0, SP = 0.0;
        long long C = 0;
        #pragma unroll
        for (int j = 0; j < RED_THREADS / 32; j++) { SA += d_sa[j]; SP += d_sp[j]; C += d_c[j]; }

        double pos = (double)C;
        double neg = n_total - pos;
        bool valid = (pos > 0.0) && (neg > 0.0);
        double sum_neg = SA - SP;
        double denom = valid ? pos * neg : 1.0;
        double loss = DETA * (pos * sum_neg - neg * SP) / denom;
        out[0] = valid ? (float)loss : 0.0f;

        g_done = 0;   // reset for next graph replay
    }
}

extern "C" void kernel_launch(void* const* d_in, const int* in_sizes, int n_in,
                              void* d_out, int out_size)
{
    const float* y   = (const float*)d_in[0];
    const int*   lab = (const int*)d_in[1];
    int n = in_sizes[0];

    int nvec8 = n >> 3;
    int tail  = n & 7;

    fused_loss_kernel<<<RED_BLOCKS, RED_THREADS>>>(
        y, lab, nvec8, tail, (float*)d_out, (double)n);
}